// round 5
// baseline (speedup 1.0000x reference)
#include <cuda_runtime.h>
#include <cstdint>

// Problem constants (fixed by the reference setup)
#define NV 150000          // total active voxels
#define SZc 41
#define SYc 1600
#define SXc 1408
#define HBITS 19
#define HSIZE (1 << HBITS) // 524288 hash slots; empty = 0, key = lin+1
#define HMASK (HSIZE - 1)
#define BSHIFT 13
#define NBK 45100          // rank buckets; max lin 369,459,199 -> bucket 45099
#define NCHUNK 89          // ceil(NBK/512) scan chunks
#define GRID 148
#define TB 256
#define STRIDE (GRID * TB)

// ---------------- static device scratch (zero-initialized; kernel leaves it clean) ----------------
__device__ int   g_hkey[HSIZE];      // 0 = empty, else lin+1
__device__ int   g_hval[HSIZE];
__device__ int   g_slot[NV];
__device__ int   g_lin[NV];
__device__ int   g_cnt[NV];
__device__ int   g_nbr[NV * 27];     // packed (k<<18)|row
__device__ int   g_hist[NBK];
__device__ int   g_scan[NBK + 1];
__device__ int   g_bsum[NCHUNK];
__device__ int   g_bfill[NBK];
__device__ int   g_blin[NV];
__device__ float g_y0[NV * 16];
__device__ float g_xa[NV * 16];
__device__ float g_p0[GRID * 32];    // conv0 BN partials
__device__ float g_p1[GRID * 32];    // conv1 BN partials
__device__ unsigned g_cbar;          // barrier counter (self-resets to 0)
__device__ unsigned g_sbar;          // barrier sense (persists; read at kernel start)

__device__ __forceinline__ unsigned hash_of(int key) {
    return ((unsigned)key * 2654435761u) >> (32 - HBITS);
}

// Global barrier: sense-reversing, self-resetting. All GRID blocks co-resident.
#define GBAR() do {                                                         \
    __threadfence();                                                        \
    __syncthreads();                                                        \
    if (tid == 0) {                                                         \
        unsigned ns = s_sense ^ 1u;                                         \
        s_sense = ns;                                                       \
        if (atomicAdd(&g_cbar, 1u) == GRID - 1u) {                          \
            g_cbar = 0u;                                                    \
            __threadfence();                                                \
            *(volatile unsigned*)&g_sbar = ns;                              \
        } else {                                                            \
            while (*(volatile unsigned*)&g_sbar != ns) __nanosleep(32);     \
        }                                                                   \
    }                                                                       \
    __syncthreads();                                                        \
    __threadfence();                                                        \
} while (0)

// Deterministic per-block BN partial: warp tree + cross-warp, publish 32 floats.
__device__ __forceinline__ void bn_publish(float s[16], float q[16],
                                           float* part, float sred[8][32]) {
    int tid = threadIdx.x;
    #pragma unroll
    for (int c = 0; c < 16; c++) {
        #pragma unroll
        for (int off = 16; off > 0; off >>= 1) {
            s[c] += __shfl_down_sync(0xffffffffu, s[c], off);
            q[c] += __shfl_down_sync(0xffffffffu, q[c], off);
        }
    }
    int wp = tid >> 5, lane = tid & 31;
    if (lane == 0) {
        #pragma unroll
        for (int c = 0; c < 16; c++) { sred[wp][c] = s[c]; sred[wp][16 + c] = q[c]; }
    }
    __syncthreads();
    if (wp == 0) {
        float t = 0.f;
        #pragma unroll
        for (int k = 0; k < 8; k++) t += sred[k][lane];
        part[blockIdx.x * 32 + lane] = t;
    }
}

__global__ __launch_bounds__(TB, 1) void mega(
    const float* __restrict__ feats, const int* __restrict__ inds,
    const float* __restrict__ w_in,
    const float* __restrict__ g0, const float* __restrict__ b0,
    const float* __restrict__ w1,
    const float* __restrict__ g1, const float* __restrict__ b1,
    float* __restrict__ out)
{
    __shared__ float s_w[27 * 256];     // conv weights (conv0 uses first 27*64)
    __shared__ float s_red[8][32];
    __shared__ int   s_scan[256];
    __shared__ float s_ss[32];          // scale[16], shift[16]
    __shared__ unsigned s_sense;

    const int tid = threadIdx.x;
    const int gid = blockIdx.x * TB + tid;
    const int b   = blockIdx.x;

    if (tid == 0) s_sense = *(volatile unsigned*)&g_sbar;
    __syncthreads();

    // ---- Phase A: linearize + hash insert + bucket histogram ----
    for (int j = gid; j < NV; j += STRIDE) {
        int4 id = reinterpret_cast<const int4*>(inds)[j];
        int l = ((id.x * SZc + id.y) * SYc + id.z) * SXc + id.w;
        g_lin[j] = l;
        unsigned slot = hash_of(l);
        while (true) {
            int old = atomicCAS(&g_hkey[slot], 0, l + 1);
            if (old == 0) { g_hval[slot] = j; g_slot[j] = slot; break; }
            slot = (slot + 1) & HMASK;
        }
        atomicAdd(&g_hist[l >> BSHIFT], 1);
    }
    GBAR();  // 1

    // ---- Phase B1: chunk-local exclusive scan (512 entries/block) ----
    if (b < NCHUNK) {
        int base = b * 512;
        int i0 = base + 2 * tid, i1 = i0 + 1;
        int v0 = (i0 < NBK) ? g_hist[i0] : 0;
        int v1 = (i1 < NBK) ? g_hist[i1] : 0;
        int ps = v0 + v1;
        s_scan[tid] = ps;
        __syncthreads();
        for (int off = 1; off < 256; off <<= 1) {
            int x = (tid >= off) ? s_scan[tid - off] : 0;
            __syncthreads();
            if (tid >= off) s_scan[tid] += x;
            __syncthreads();
        }
        int incl = s_scan[tid];
        int ex = incl - ps;
        if (i0 < NBK) g_scan[i0] = ex;
        if (i1 < NBK) g_scan[i1] = ex + v0;
        if (tid == 255) g_bsum[b] = incl;
    }
    GBAR();  // 2

    // ---- Phase B2: add chunk-prefix (parallel reduce of preceding aggregates) ----
    if (b < NCHUNK) {
        s_scan[tid] = (tid < b) ? g_bsum[tid] : 0;   // b <= 88 < 256
        __syncthreads();
        for (int off = 128; off > 0; off >>= 1) {
            if (tid < off) s_scan[tid] += s_scan[tid + off];
            __syncthreads();
        }
        int offv = s_scan[0];
        int base = b * 512;
        int i0 = base + 2 * tid, i1 = i0 + 1;
        if (i0 < NBK) g_scan[i0] += offv;
        if (i1 < NBK) g_scan[i1] += offv;
        if (b == 0 && tid == 0) g_scan[NBK] = NV;
    }
    GBAR();  // 3

    // ---- Phase C: scatter lins into rank buckets + build rulebook ----
    for (int j = gid; j < NV; j += STRIDE) {
        int4 id = reinterpret_cast<const int4*>(inds)[j];
        int l = g_lin[j];
        int bk = l >> BSHIFT;
        int p = atomicAdd(&g_bfill[bk], 1);
        g_blin[g_scan[bk] + p] = l;
        int c = 0;
        int base = j * 27;
        #pragma unroll
        for (int dz = -1; dz <= 1; dz++) {
            int z = id.y + dz;
            #pragma unroll
            for (int dy = -1; dy <= 1; dy++) {
                int y = id.z + dy;
                #pragma unroll
                for (int dx = -1; dx <= 1; dx++) {
                    if (dz == 0 && dy == 0 && dx == 0) {
                        g_nbr[base + c] = (13 << 18) | j;
                        c++;
                        continue;
                    }
                    int x = id.w + dx;
                    if (z < 0 || z >= SZc || y < 0 || y >= SYc || x < 0 || x >= SXc) continue;
                    int nl = ((id.x * SZc + z) * SYc + y) * SXc + x;
                    unsigned slot = hash_of(nl);
                    int r = -1;
                    int tgt = nl + 1;
                    while (true) {
                        int key = g_hkey[slot];
                        if (key == tgt) { r = g_hval[slot]; break; }
                        if (key == 0) break;
                        slot = (slot + 1) & HMASK;
                    }
                    if (r >= 0) {
                        int k = ((dz + 1) * 3 + (dy + 1)) * 3 + (dx + 1);
                        g_nbr[base + c] = (k << 18) | r;
                        c++;
                    }
                }
            }
        }
        g_cnt[j] = c;
    }
    GBAR();  // 4

    // ---- Phase D: conv0 (4->16) + publish BN0 partials ----
    for (int i = tid; i < 27 * 64; i += TB) s_w[i] = w_in[i];
    __syncthreads();
    {
        float s[16], q[16];
        #pragma unroll
        for (int c = 0; c < 16; c++) { s[c] = 0.f; q[c] = 0.f; }
        for (int j = gid; j < NV; j += STRIDE) {
            float acc[16];
            #pragma unroll
            for (int o = 0; o < 16; o++) acc[o] = 0.f;
            int cn = g_cnt[j];
            int base = j * 27;
            for (int i = 0; i < cn; i++) {
                int p = g_nbr[base + i];
                int k = p >> 18;
                int r = p & 0x3FFFF;
                float4 f = reinterpret_cast<const float4*>(feats)[r];
                const float* wk = &s_w[k * 64];
                #pragma unroll
                for (int o = 0; o < 16; o++)
                    acc[o] += f.x * wk[o] + f.y * wk[16 + o] + f.z * wk[32 + o] + f.w * wk[48 + o];
            }
            float4* dst = reinterpret_cast<float4*>(&g_y0[j * 16]);
            #pragma unroll
            for (int qq = 0; qq < 4; qq++)
                dst[qq] = make_float4(acc[qq * 4], acc[qq * 4 + 1], acc[qq * 4 + 2], acc[qq * 4 + 3]);
            #pragma unroll
            for (int c = 0; c < 16; c++) { s[c] += acc[c]; q[c] += acc[c] * acc[c]; }
        }
        bn_publish(s, q, g_p0, s_red);
    }
    GBAR();  // 5

    // ---- Phase E/F: local BN0 scale/shift, conv1 (16->16) + publish BN1 partials ----
    if (tid < 16) {
        double ds = 0.0, dq = 0.0;
        for (int k = 0; k < GRID; k++) {
            ds += (double)g_p0[k * 32 + tid];
            dq += (double)g_p0[k * 32 + 16 + tid];
        }
        double m = ds / (double)NV;
        double v = dq / (double)NV - m * m;
        double inv = 1.0 / sqrt(v + 1e-3);
        float sc = g0[tid] * (float)inv;
        s_ss[tid] = sc;
        s_ss[16 + tid] = b0[tid] - (float)m * sc;
    }
    for (int i = tid; i < 27 * 256; i += TB) s_w[i] = w1[i];
    __syncthreads();
    {
        float s[16], q[16];
        #pragma unroll
        for (int c = 0; c < 16; c++) { s[c] = 0.f; q[c] = 0.f; }
        for (int j = gid; j < NV; j += STRIDE) {
            float acc[16];
            #pragma unroll
            for (int o = 0; o < 16; o++) acc[o] = 0.f;
            int cn = g_cnt[j];
            int base = j * 27;
            for (int i = 0; i < cn; i++) {
                int p = g_nbr[base + i];
                int k = p >> 18;
                int r = p & 0x3FFFF;
                const float4* xr = reinterpret_cast<const float4*>(&g_y0[r * 16]);
                float xv[16];
                #pragma unroll
                for (int qq = 0; qq < 4; qq++) {
                    float4 v = xr[qq];
                    int c4 = qq * 4;
                    xv[c4 + 0] = fmaxf(v.x * s_ss[c4 + 0] + s_ss[16 + c4 + 0], 0.f);
                    xv[c4 + 1] = fmaxf(v.y * s_ss[c4 + 1] + s_ss[16 + c4 + 1], 0.f);
                    xv[c4 + 2] = fmaxf(v.z * s_ss[c4 + 2] + s_ss[16 + c4 + 2], 0.f);
                    xv[c4 + 3] = fmaxf(v.w * s_ss[c4 + 3] + s_ss[16 + c4 + 3], 0.f);
                }
                const float* wk = &s_w[k * 256];
                #pragma unroll
                for (int c = 0; c < 16; c++) {
                    #pragma unroll
                    for (int o = 0; o < 16; o++) acc[o] += xv[c] * wk[c * 16 + o];
                }
            }
            float4* dst = reinterpret_cast<float4*>(&g_xa[j * 16]);
            #pragma unroll
            for (int qq = 0; qq < 4; qq++)
                dst[qq] = make_float4(acc[qq * 4], acc[qq * 4 + 1], acc[qq * 4 + 2], acc[qq * 4 + 3]);
            #pragma unroll
            for (int c = 0; c < 16; c++) { s[c] += acc[c]; q[c] += acc[c] * acc[c]; }
        }
        bn_publish(s, q, g_p1, s_red);
    }
    GBAR();  // 6

    // ---- Phase G: local BN1 scale/shift, rank lookup + affine + duplicated out, cleanup ----
    if (tid < 16) {
        double ds = 0.0, dq = 0.0;
        for (int k = 0; k < GRID; k++) {
            ds += (double)g_p1[k * 32 + tid];
            dq += (double)g_p1[k * 32 + 16 + tid];
        }
        double m = ds / (double)NV;
        double v = dq / (double)NV - m * m;
        double inv = 1.0 / sqrt(v + 1e-3);
        float sc = g1[tid] * (float)inv;
        s_ss[tid] = sc;
        s_ss[16 + tid] = b1[tid] - (float)m * sc;
    }
    __syncthreads();
    for (int j = gid; j < NV; j += STRIDE) {
        int l = g_lin[j];
        int bk = l >> BSHIFT;
        int s0 = g_scan[bk], s1 = g_scan[bk + 1];
        int c = 0;
        for (int t = s0; t < s1; t++) c += (g_blin[t] < l);
        int r = s0 + c;
        const float4* xr = reinterpret_cast<const float4*>(&g_xa[r * 16]);
        float4* d0 = reinterpret_cast<float4*>(&out[(size_t)j * 16]);
        float4* d1 = reinterpret_cast<float4*>(&out[(size_t)(j + NV) * 16]);
        #pragma unroll
        for (int qq = 0; qq < 4; qq++) {
            float4 v = xr[qq];
            int c4 = qq * 4;
            v.x = fmaxf(v.x * s_ss[c4 + 0] + s_ss[16 + c4 + 0], 0.f);
            v.y = fmaxf(v.y * s_ss[c4 + 1] + s_ss[16 + c4 + 1], 0.f);
            v.z = fmaxf(v.z * s_ss[c4 + 2] + s_ss[16 + c4 + 2], 0.f);
            v.w = fmaxf(v.w * s_ss[c4 + 3] + s_ss[16 + c4 + 3], 0.f);
            d0[qq] = v;
            d1[qq] = v;
        }
        // cleanup: clear this voxel's hash slot for the next replay
        g_hkey[g_slot[j]] = 0;
    }
    for (int i = gid; i < NBK; i += STRIDE) { g_hist[i] = 0; g_bfill[i] = 0; }
}

extern "C" void kernel_launch(void* const* d_in, const int* in_sizes, int n_in,
                              void* d_out, int out_size) {
    const float* feats = (const float*)d_in[0];
    const int*   inds  = (const int*)d_in[1];
    const float* w_in  = (const float*)d_in[2];
    const float* g0    = (const float*)d_in[3];
    const float* b0    = (const float*)d_in[4];
    const float* w1    = (const float*)d_in[5];
    const float* g1    = (const float*)d_in[6];
    const float* b1    = (const float*)d_in[7];
    // w2/g2/b2 (d_in[8..10]) are dead in the reference: cat_tensors' inverse
    // indices only ever select rows of xa.
    float* out = (float*)d_out;

    mega<<<GRID, TB>>>(feats, inds, w_in, g0, b0, w1, g1, b1, out);
}

// round 7
// speedup vs baseline: 1.0690x; 1.0690x over previous
#include <cuda_runtime.h>
#include <cstdint>

// Problem constants (fixed by the reference setup)
#define NV 150000          // total active voxels
#define SZc 41
#define SYc 1600
#define SXc 1408
#define HBITS 19
#define HSIZE (1 << HBITS) // 524288 hash slots; empty = 0, key = lin+1
#define HMASK (HSIZE - 1)
#define BSHIFT 13
#define NBK 45100          // rank buckets; max lin 369,459,199 -> bucket 45099
#define NCHUNK 89          // ceil(NBK/512) scan chunks
#define GRID 444           // 3 CTAs/SM x 148 SMs, all co-resident
#define TB 256
#define STRIDE (GRID * TB)

// ---------------- static device scratch (zero-initialized; kernel leaves it clean) ----------------
__device__ int   g_hkey[HSIZE];      // 0 = empty, else lin+1
__device__ int   g_hval[HSIZE];
__device__ int   g_slot[NV];
__device__ int   g_lin[NV];
__device__ int   g_cnt[NV];
__device__ int   g_nbr[NV * 27];     // packed (k<<18)|row
__device__ int   g_hist[NBK];
__device__ int   g_scan[NBK];        // chunk-local exclusive scan
__device__ int   g_bsum[NCHUNK];     // chunk aggregates
__device__ int   g_bfill[NBK];
__device__ int   g_blin[NV];
__device__ float g_y0[NV * 16];
__device__ float g_xa[NV * 16];
__device__ float g_p0[GRID * 32];    // conv0 BN partials
__device__ float g_p1[GRID * 32];    // conv1 BN partials
__device__ unsigned g_cbar;          // barrier counter (self-resets to 0)
__device__ unsigned g_sbar;          // barrier sense (persists; read at kernel start)

__device__ __forceinline__ unsigned hash_of(int key) {
    return ((unsigned)key * 2654435761u) >> (32 - HBITS);
}

// Global barrier: sense-reversing, self-resetting. All GRID blocks co-resident.
#define GBAR() do {                                                         \
    __threadfence();                                                        \
    __syncthreads();                                                        \
    if (tid == 0) {                                                         \
        unsigned ns = s_sense ^ 1u;                                         \
        s_sense = ns;                                                       \
        if (atomicAdd(&g_cbar, 1u) == GRID - 1u) {                          \
            g_cbar = 0u;                                                    \
            __threadfence();                                                \
            *(volatile unsigned*)&g_sbar = ns;                              \
        } else {                                                            \
            while (*(volatile unsigned*)&g_sbar != ns) __nanosleep(32);     \
        }                                                                   \
    }                                                                       \
    __syncthreads();                                                        \
    __threadfence();                                                        \
} while (0)

// Deterministic per-block BN partial publish: warp tree + cross-warp.
__device__ __forceinline__ void bn_publish(float s[16], float q[16],
                                           float* part, float sred[8][32]) {
    int tid = threadIdx.x;
    #pragma unroll
    for (int c = 0; c < 16; c++) {
        #pragma unroll
        for (int off = 16; off > 0; off >>= 1) {
            s[c] += __shfl_down_sync(0xffffffffu, s[c], off);
            q[c] += __shfl_down_sync(0xffffffffu, q[c], off);
        }
    }
    int wp = tid >> 5, lane = tid & 31;
    if (lane == 0) {
        #pragma unroll
        for (int c = 0; c < 16; c++) { sred[wp][c] = s[c]; sred[wp][16 + c] = q[c]; }
    }
    __syncthreads();
    if (wp == 0) {
        float t = 0.f;
        #pragma unroll
        for (int k = 0; k < 8; k++) t += sred[k][lane];
        part[blockIdx.x * 32 + lane] = t;
    }
    __syncthreads();
}

// Redundant (per-block) BN finalize: fixed-order double sum over GRID partials.
__device__ __forceinline__ void bn_finalize(const float* part,
                                            const float* __restrict__ g,
                                            const float* __restrict__ b,
                                            float* s_ss) {
    int tid = threadIdx.x;
    if (tid < 16) {
        double ds = 0.0, dq = 0.0;
        for (int k = 0; k < GRID; k++) {
            ds += (double)part[k * 32 + tid];
            dq += (double)part[k * 32 + 16 + tid];
        }
        double m = ds / (double)NV;
        double v = dq / (double)NV - m * m;
        double inv = 1.0 / sqrt(v + 1e-3);
        float sc = g[tid] * (float)inv;
        s_ss[tid] = sc;
        s_ss[16 + tid] = b[tid] - (float)m * sc;
    }
}

__global__ __launch_bounds__(TB, 3) void mega(
    const float* __restrict__ feats, const int* __restrict__ inds,
    const float* __restrict__ w_in,
    const float* __restrict__ g0, const float* __restrict__ b0,
    const float* __restrict__ w1,
    const float* __restrict__ g1, const float* __restrict__ b1,
    float* __restrict__ out)
{
    __shared__ float s_w[27 * 256];     // conv weights (conv0 uses first 27*64)
    __shared__ float s_red[8][32];
    __shared__ int   s_scan[256];
    __shared__ float s_ss[32];          // scale[16], shift[16]
    __shared__ int   s_cpref[NCHUNK];   // exclusive prefix of chunk aggregates
    __shared__ unsigned s_sense;

    const int tid = threadIdx.x;
    const int gid = blockIdx.x * TB + tid;
    const int b   = blockIdx.x;

    if (tid == 0) s_sense = *(volatile unsigned*)&g_sbar;
    __syncthreads();

    // ---- Phase A: linearize + hash insert + bucket histogram ----
    for (int j = gid; j < NV; j += STRIDE) {
        int4 id = reinterpret_cast<const int4*>(inds)[j];
        int l = ((id.x * SZc + id.y) * SYc + id.z) * SXc + id.w;
        g_lin[j] = l;
        unsigned slot = hash_of(l);
        while (true) {
            int old = atomicCAS(&g_hkey[slot], 0, l + 1);
            if (old == 0) { g_hval[slot] = j; g_slot[j] = slot; break; }
            slot = (slot + 1) & HMASK;
        }
        atomicAdd(&g_hist[l >> BSHIFT], 1);
    }
    GBAR();  // 1

    // ---- Phase B: chunk-local exclusive scan (512 entries per chunk, 89 chunks) ----
    if (b < NCHUNK) {
        int base = b * 512;
        int i0 = base + 2 * tid, i1 = i0 + 1;
        int v0 = (i0 < NBK) ? g_hist[i0] : 0;
        int v1 = (i1 < NBK) ? g_hist[i1] : 0;
        int ps = v0 + v1;
        s_scan[tid] = ps;
        __syncthreads();
        for (int off = 1; off < 256; off <<= 1) {
            int x = (tid >= off) ? s_scan[tid - off] : 0;
            __syncthreads();
            if (tid >= off) s_scan[tid] += x;
            __syncthreads();
        }
        int incl = s_scan[tid];
        int ex = incl - ps;
        if (i0 < NBK) g_scan[i0] = ex;
        if (i1 < NBK) g_scan[i1] = ex + v0;
        if (tid == 255) g_bsum[b] = incl;
    }
    GBAR();  // 2

    // ---- every block: local exclusive prefix of the 89 chunk aggregates ----
    if (tid < NCHUNK) s_cpref[tid] = g_bsum[tid];
    __syncthreads();
    if (tid == 0) {
        int run = 0;
        #pragma unroll 1
        for (int k = 0; k < NCHUNK; k++) { int v = s_cpref[k]; s_cpref[k] = run; run += v; }
    }
    // load conv0 weights while prefix settles
    for (int i = tid; i < 27 * 64; i += TB) s_w[i] = w_in[i];
    __syncthreads();

    // ---- Phase C: scatter + rulebook + conv0 fused (conv0 gathers read only input feats) ----
    for (int j = gid; j < NV; j += STRIDE) {
        int4 id = reinterpret_cast<const int4*>(inds)[j];
        int l = g_lin[j];
        int bk = l >> BSHIFT;
        int fs = g_scan[bk] + s_cpref[bk >> 9];
        int p = atomicAdd(&g_bfill[bk], 1);
        g_blin[fs + p] = l;

        float acc[16];
        #pragma unroll
        for (int o = 0; o < 16; o++) acc[o] = 0.f;
        int c = 0;
        int base = j * 27;
        #pragma unroll
        for (int dz = -1; dz <= 1; dz++) {
            int z = id.y + dz;
            #pragma unroll
            for (int dy = -1; dy <= 1; dy++) {
                int y = id.z + dy;
                #pragma unroll
                for (int dx = -1; dx <= 1; dx++) {
                    int r = -1;
                    int k = ((dz + 1) * 3 + (dy + 1)) * 3 + (dx + 1);
                    if (dz == 0 && dy == 0 && dx == 0) {
                        r = j;
                    } else {
                        int x = id.w + dx;
                        if (z < 0 || z >= SZc || y < 0 || y >= SYc || x < 0 || x >= SXc) continue;
                        int nl = ((id.x * SZc + z) * SYc + y) * SXc + x;
                        unsigned slot = hash_of(nl);
                        int tgt = nl + 1;
                        while (true) {
                            int key = g_hkey[slot];
                            if (key == tgt) { r = g_hval[slot]; break; }
                            if (key == 0) break;
                            slot = (slot + 1) & HMASK;
                        }
                        if (r < 0) continue;
                    }
                    g_nbr[base + c] = (k << 18) | r;
                    c++;
                    float4 f = reinterpret_cast<const float4*>(feats)[r];
                    const float* wk = &s_w[k * 64];
                    #pragma unroll
                    for (int o = 0; o < 16; o++)
                        acc[o] += f.x * wk[o] + f.y * wk[16 + o] + f.z * wk[32 + o] + f.w * wk[48 + o];
                }
            }
        }
        g_cnt[j] = c;
        float4* dst = reinterpret_cast<float4*>(&g_y0[j * 16]);
        #pragma unroll
        for (int qq = 0; qq < 4; qq++)
            dst[qq] = make_float4(acc[qq * 4], acc[qq * 4 + 1], acc[qq * 4 + 2], acc[qq * 4 + 3]);
    }
    // BN0 partials: re-read own rows (no barrier needed: same j-range this thread wrote)
    {
        float s[16], q[16];
        #pragma unroll
        for (int c = 0; c < 16; c++) { s[c] = 0.f; q[c] = 0.f; }
        for (int j = gid; j < NV; j += STRIDE) {
            const float4* rr = reinterpret_cast<const float4*>(&g_y0[j * 16]);
            #pragma unroll
            for (int qq = 0; qq < 4; qq++) {
                float4 v = rr[qq];
                int c4 = qq * 4;
                s[c4 + 0] += v.x; q[c4 + 0] += v.x * v.x;
                s[c4 + 1] += v.y; q[c4 + 1] += v.y * v.y;
                s[c4 + 2] += v.z; q[c4 + 2] += v.z * v.z;
                s[c4 + 3] += v.w; q[c4 + 3] += v.w * v.w;
            }
        }
        bn_publish(s, q, g_p0, s_red);
    }
    GBAR();  // 3

    // ---- Phase D: conv1 (16->16) with inline BN0+ReLU on gathers ----
    bn_finalize(g_p0, g0, b0, s_ss);
    for (int i = tid; i < 27 * 256; i += TB) s_w[i] = w1[i];
    __syncthreads();
    for (int j = gid; j < NV; j += STRIDE) {
        float acc[16];
        #pragma unroll
        for (int o = 0; o < 16; o++) acc[o] = 0.f;
        int cn = g_cnt[j];
        int base = j * 27;
        for (int i = 0; i < cn; i++) {
            int p = g_nbr[base + i];
            int k = p >> 18;
            int r = p & 0x3FFFF;
            const float4* xr = reinterpret_cast<const float4*>(&g_y0[r * 16]);
            const float* wk = &s_w[k * 256];
            #pragma unroll
            for (int qq = 0; qq < 4; qq++) {
                float4 v = xr[qq];
                int c4 = qq * 4;
                float x0 = fmaxf(v.x * s_ss[c4 + 0] + s_ss[16 + c4 + 0], 0.f);
                float x1 = fmaxf(v.y * s_ss[c4 + 1] + s_ss[16 + c4 + 1], 0.f);
                float x2 = fmaxf(v.z * s_ss[c4 + 2] + s_ss[16 + c4 + 2], 0.f);
                float x3 = fmaxf(v.w * s_ss[c4 + 3] + s_ss[16 + c4 + 3], 0.f);
                const float* w0 = wk + (c4 + 0) * 16;
                const float* w1p = wk + (c4 + 1) * 16;
                const float* w2 = wk + (c4 + 2) * 16;
                const float* w3 = wk + (c4 + 3) * 16;
                #pragma unroll
                for (int o = 0; o < 16; o++)
                    acc[o] += x0 * w0[o] + x1 * w1p[o] + x2 * w2[o] + x3 * w3[o];
            }
        }
        float4* dst = reinterpret_cast<float4*>(&g_xa[j * 16]);
        #pragma unroll
        for (int qq = 0; qq < 4; qq++)
            dst[qq] = make_float4(acc[qq * 4], acc[qq * 4 + 1], acc[qq * 4 + 2], acc[qq * 4 + 3]);
    }
    // BN1 partials: re-read own rows
    {
        float s[16], q[16];
        #pragma unroll
        for (int c = 0; c < 16; c++) { s[c] = 0.f; q[c] = 0.f; }
        for (int j = gid; j < NV; j += STRIDE) {
            const float4* rr = reinterpret_cast<const float4*>(&g_xa[j * 16]);
            #pragma unroll
            for (int qq = 0; qq < 4; qq++) {
                float4 v = rr[qq];
                int c4 = qq * 4;
                s[c4 + 0] += v.x; q[c4 + 0] += v.x * v.x;
                s[c4 + 1] += v.y; q[c4 + 1] += v.y * v.y;
                s[c4 + 2] += v.z; q[c4 + 2] += v.z * v.z;
                s[c4 + 3] += v.w; q[c4 + 3] += v.w * v.w;
            }
        }
        bn_publish(s, q, g_p1, s_red);
    }
    GBAR();  // 4

    // ---- Phase E: BN1 finalize, rank lookup + affine + duplicated out, cleanup ----
    bn_finalize(g_p1, g1, b1, s_ss);
    __syncthreads();
    for (int j = gid; j < NV; j += STRIDE) {
        int l = g_lin[j];
        int bk = l >> BSHIFT;
        int s0 = g_scan[bk] + s_cpref[bk >> 9];
        int s1 = (bk + 1 == NBK) ? NV : (g_scan[bk + 1] + s_cpref[(bk + 1) >> 9]);
        int c = 0;
        for (int t = s0; t < s1; t++) c += (g_blin[t] < l);
        int r = s0 + c;
        const float4* xr = reinterpret_cast<const float4*>(&g_xa[r * 16]);
        float4* d0 = reinterpret_cast<float4*>(&out[(size_t)j * 16]);
        float4* d1 = reinterpret_cast<float4*>(&out[(size_t)(j + NV) * 16]);
        #pragma unroll
        for (int qq = 0; qq < 4; qq++) {
            float4 v = xr[qq];
            int c4 = qq * 4;
            v.x = fmaxf(v.x * s_ss[c4 + 0] + s_ss[16 + c4 + 0], 0.f);
            v.y = fmaxf(v.y * s_ss[c4 + 1] + s_ss[16 + c4 + 1], 0.f);
            v.z = fmaxf(v.z * s_ss[c4 + 2] + s_ss[16 + c4 + 2], 0.f);
            v.w = fmaxf(v.w * s_ss[c4 + 3] + s_ss[16 + c4 + 3], 0.f);
            d0[qq] = v;
            d1[qq] = v;
        }
        g_hkey[g_slot[j]] = 0;   // clear hash slot for next replay
    }
    for (int i = gid; i < NBK; i += STRIDE) { g_hist[i] = 0; g_bfill[i] = 0; }
}

extern "C" void kernel_launch(void* const* d_in, const int* in_sizes, int n_in,
                              void* d_out, int out_size) {
    const float* feats = (const float*)d_in[0];
    const int*   inds  = (const int*)d_in[1];
    const float* w_in  = (const float*)d_in[2];
    const float* g0    = (const float*)d_in[3];
    const float* b0    = (const float*)d_in[4];
    const float* w1    = (const float*)d_in[5];
    const float* g1    = (const float*)d_in[6];
    const float* b1    = (const float*)d_in[7];
    // w2/g2/b2 (d_in[8..10]) are dead in the reference: cat_tensors' inverse
    // indices only ever select rows of xa.
    float* out = (float*)d_out;

    mega<<<GRID, TB>>>(feats, inds, w_in, g0, b0, w1, g1, b1, out);
}

// round 9
// speedup vs baseline: 1.2453x; 1.1649x over previous
#include <cuda_runtime.h>
#include <cstdint>

// Problem constants (fixed by the reference setup)
#define NV 150000          // total active voxels
#define SZc 41
#define SYc 1600
#define SXc 1408
#define HBITS 19
#define HSIZE (1 << HBITS) // 524288 hash slots; empty = 0, key = lin+1
#define HMASK (HSIZE - 1)
#define BSHIFT 13
#define NBK 45100          // rank buckets; max lin 369,459,199 -> bucket 45099
#define BCAP 32            // bucket capacity (avg fill 3.3; overflow P ~ 1e-20)
#define NCHUNK 89          // ceil(NBK/512) scan chunks
#define GRID 444           // 3 CTAs/SM x 148 SMs, all co-resident
#define TB 256
#define STRIDE (GRID * TB)

// ---------------- static device scratch (zero-initialized; kernel leaves it clean) ----------------
__device__ int   g_hkey[HSIZE];      // 0 = empty, else lin+1
__device__ int   g_hval[HSIZE];
__device__ int   g_slot[NV];
__device__ int   g_lin[NV];
__device__ int   g_cnt[NV];
__device__ int   g_nbr[NV * 27];     // packed (k<<18)|row
__device__ int   g_bfill[NBK];       // bucket fill counts (cleared at end)
__device__ int   g_blin2[NBK * BCAP];// bucket contents (lins, unordered)
__device__ int   g_scan[NBK];        // chunk-local exclusive scan of bucket counts
__device__ int   g_bsum[NCHUNK];     // chunk aggregates
__device__ float g_y0[NV * 16];
__device__ float g_xa[NV * 16];
__device__ float g_p0[GRID * 32];    // conv0 BN partials
__device__ float g_p1[GRID * 32];    // conv1 BN partials
__device__ unsigned g_cbar;          // barrier counter (self-resets to 0)
__device__ unsigned g_sbar;          // barrier sense (persists; read at kernel start)

__device__ __forceinline__ unsigned hash_of(int key) {
    return ((unsigned)key * 2654435761u) >> (32 - HBITS);
}

// Global barrier: sense-reversing, self-resetting. All GRID blocks co-resident.
#define GBAR() do {                                                         \
    __threadfence();                                                        \
    __syncthreads();                                                        \
    if (tid == 0) {                                                         \
        unsigned ns = s_sense ^ 1u;                                         \
        s_sense = ns;                                                       \
        if (atomicAdd(&g_cbar, 1u) == GRID - 1u) {                          \
            g_cbar = 0u;                                                    \
            __threadfence();                                                \
            *(volatile unsigned*)&g_sbar = ns;                              \
        } else {                                                            \
            while (*(volatile unsigned*)&g_sbar != ns) __nanosleep(32);     \
        }                                                                   \
    }                                                                       \
    __syncthreads();                                                        \
    __threadfence();                                                        \
} while (0)

// Deterministic per-block BN partial publish: warp tree + cross-warp.
__device__ __forceinline__ void bn_publish(float s[16], float q[16],
                                           float* part, float sred[8][32]) {
    int tid = threadIdx.x;
    #pragma unroll
    for (int c = 0; c < 16; c++) {
        #pragma unroll
        for (int off = 16; off > 0; off >>= 1) {
            s[c] += __shfl_down_sync(0xffffffffu, s[c], off);
            q[c] += __shfl_down_sync(0xffffffffu, q[c], off);
        }
    }
    int wp = tid >> 5, lane = tid & 31;
    if (lane == 0) {
        #pragma unroll
        for (int c = 0; c < 16; c++) { sred[wp][c] = s[c]; sred[wp][16 + c] = q[c]; }
    }
    __syncthreads();
    if (wp == 0) {
        float t = 0.f;
        #pragma unroll
        for (int k = 0; k < 8; k++) t += sred[k][lane];
        part[blockIdx.x * 32 + lane] = t;
    }
    __syncthreads();
}

// Redundant PER-BLOCK parallel finalize, bitwise deterministic:
// 8 groups sum fixed strided subsets of the GRID partials, fixed-order combine.
__device__ __forceinline__ void bn_finalize_par(const float* part,
                                                const float* __restrict__ g,
                                                const float* __restrict__ b,
                                                float* s_ss, double sredd[8][32]) {
    int tid = threadIdx.x;
    int col = tid & 31, grp = tid >> 5;
    double a = 0.0;
    for (int k = grp; k < GRID; k += 8) a += (double)part[k * 32 + col];
    sredd[grp][col] = a;
    __syncthreads();
    if (tid < 32) {
        double t = 0.0;
        #pragma unroll
        for (int gg = 0; gg < 8; gg++) t += sredd[gg][tid];
        sredd[0][tid] = t;
    }
    __syncthreads();
    if (tid < 16) {
        double m = sredd[0][tid] / (double)NV;
        double v = sredd[0][16 + tid] / (double)NV - m * m;
        double inv = 1.0 / sqrt(v + 1e-3);
        float sc = g[tid] * (float)inv;
        s_ss[tid] = sc;
        s_ss[16 + tid] = b[tid] - (float)m * sc;
    }
    __syncthreads();
}

__global__ __launch_bounds__(TB, 3) void mega(
    const float* __restrict__ feats, const int* __restrict__ inds,
    const float* __restrict__ w_in,
    const float* __restrict__ g0, const float* __restrict__ b0,
    const float* __restrict__ w1,
    const float* __restrict__ g1, const float* __restrict__ b1,
    float* __restrict__ out)
{
    __shared__ float  s_w[27 * 256];    // conv weights (conv0 uses first 27*64)
    __shared__ float  s_red[8][32];     // BN publish staging
    __shared__ double s_redd[8][32];    // BN finalize staging
    __shared__ int    s_scan[256];
    __shared__ float  s_ss[32];         // scale[16], shift[16]
    __shared__ int    s_cpref[NCHUNK];  // exclusive prefix of chunk aggregates
    __shared__ unsigned s_sense;

    const int tid = threadIdx.x;
    const int gid = blockIdx.x * TB + tid;
    const int b   = blockIdx.x;

    if (tid == 0) s_sense = *(volatile unsigned*)&g_sbar;
    __syncthreads();

    // ---- Phase A: linearize + hash insert + fixed-capacity bucket scatter ----
    for (int j = gid; j < NV; j += STRIDE) {
        int4 id = reinterpret_cast<const int4*>(inds)[j];
        int l = ((id.x * SZc + id.y) * SYc + id.z) * SXc + id.w;
        g_lin[j] = l;
        unsigned slot = hash_of(l);
        while (true) {
            int old = atomicCAS(&g_hkey[slot], 0, l + 1);
            if (old == 0) { g_hval[slot] = j; g_slot[j] = slot; break; }
            slot = (slot + 1) & HMASK;
        }
        int bk = l >> BSHIFT;
        int p = atomicAdd(&g_bfill[bk], 1);
        g_blin2[(bk << 5) + p] = l;
    }
    GBAR();  // 1: hash + buckets complete

    // ---- Phase C: chunk scan (first 89 blocks) overlapped with rulebook + conv0 ----
    for (int i = tid; i < 27 * 64; i += TB) s_w[i] = w_in[i];   // conv0 weights
    if (b < NCHUNK) {
        int base = b * 512;
        int i0 = base + 2 * tid, i1 = i0 + 1;
        int v0 = (i0 < NBK) ? g_bfill[i0] : 0;
        int v1 = (i1 < NBK) ? g_bfill[i1] : 0;
        int ps = v0 + v1;
        s_scan[tid] = ps;
        __syncthreads();
        for (int off = 1; off < 256; off <<= 1) {
            int x = (tid >= off) ? s_scan[tid - off] : 0;
            __syncthreads();
            if (tid >= off) s_scan[tid] += x;
            __syncthreads();
        }
        int incl = s_scan[tid];
        int ex = incl - ps;
        if (i0 < NBK) g_scan[i0] = ex;
        if (i1 < NBK) g_scan[i1] = ex + v0;
        if (tid == 255) g_bsum[b] = incl;
    }
    __syncthreads();

    for (int j = gid; j < NV; j += STRIDE) {
        int4 id = reinterpret_cast<const int4*>(inds)[j];
        float acc[16];
        #pragma unroll
        for (int o = 0; o < 16; o++) acc[o] = 0.f;
        int c = 0;
        int base = j * 27;
        #pragma unroll
        for (int dz = -1; dz <= 1; dz++) {
            int z = id.y + dz;
            #pragma unroll
            for (int dy = -1; dy <= 1; dy++) {
                int y = id.z + dy;
                #pragma unroll
                for (int dx = -1; dx <= 1; dx++) {
                    int r = -1;
                    int k = ((dz + 1) * 3 + (dy + 1)) * 3 + (dx + 1);
                    if (dz == 0 && dy == 0 && dx == 0) {
                        r = j;
                    } else {
                        int x = id.w + dx;
                        if (z < 0 || z >= SZc || y < 0 || y >= SYc || x < 0 || x >= SXc) continue;
                        int nl = ((id.x * SZc + z) * SYc + y) * SXc + x;
                        unsigned slot = hash_of(nl);
                        int tgt = nl + 1;
                        while (true) {
                            int key = g_hkey[slot];
                            if (key == tgt) { r = g_hval[slot]; break; }
                            if (key == 0) break;
                            slot = (slot + 1) & HMASK;
                        }
                        if (r < 0) continue;
                    }
                    g_nbr[base + c] = (k << 18) | r;
                    c++;
                    float4 f = reinterpret_cast<const float4*>(feats)[r];
                    const float* wk = &s_w[k * 64];
                    #pragma unroll
                    for (int o = 0; o < 16; o++)
                        acc[o] += f.x * wk[o] + f.y * wk[16 + o] + f.z * wk[32 + o] + f.w * wk[48 + o];
                }
            }
        }
        g_cnt[j] = c;
        float4* dst = reinterpret_cast<float4*>(&g_y0[j * 16]);
        #pragma unroll
        for (int qq = 0; qq < 4; qq++)
            dst[qq] = make_float4(acc[qq * 4], acc[qq * 4 + 1], acc[qq * 4 + 2], acc[qq * 4 + 3]);
    }
    // BN0 partials: re-read own rows (same j-range this thread wrote; no barrier needed)
    {
        float s[16], q[16];
        #pragma unroll
        for (int c = 0; c < 16; c++) { s[c] = 0.f; q[c] = 0.f; }
        for (int j = gid; j < NV; j += STRIDE) {
            const float4* rr = reinterpret_cast<const float4*>(&g_y0[j * 16]);
            #pragma unroll
            for (int qq = 0; qq < 4; qq++) {
                float4 v = rr[qq];
                int c4 = qq * 4;
                s[c4 + 0] += v.x; q[c4 + 0] += v.x * v.x;
                s[c4 + 1] += v.y; q[c4 + 1] += v.y * v.y;
                s[c4 + 2] += v.z; q[c4 + 2] += v.z * v.z;
                s[c4 + 3] += v.w; q[c4 + 3] += v.w * v.w;
            }
        }
        bn_publish(s, q, g_p0, s_red);
    }
    GBAR();  // 2: y0, cnt, nbr, scan complete

    // ---- Phase D: BN0 finalize (parallel, per-block), conv1 with inline BN0+ReLU ----
    bn_finalize_par(g_p0, g0, b0, s_ss, s_redd);
    for (int i = tid; i < 27 * 256; i += TB) s_w[i] = w1[i];
    __syncthreads();
    for (int j = gid; j < NV; j += STRIDE) {
        float acc[16];
        #pragma unroll
        for (int o = 0; o < 16; o++) acc[o] = 0.f;
        int cn = g_cnt[j];
        int base = j * 27;
        for (int i = 0; i < cn; i++) {
            int p = g_nbr[base + i];
            int k = p >> 18;
            int r = p & 0x3FFFF;
            const float4* xr = reinterpret_cast<const float4*>(&g_y0[r * 16]);
            const float* wk = &s_w[k * 256];
            #pragma unroll
            for (int qq = 0; qq < 4; qq++) {
                float4 v = xr[qq];
                int c4 = qq * 4;
                float x0 = fmaxf(v.x * s_ss[c4 + 0] + s_ss[16 + c4 + 0], 0.f);
                float x1 = fmaxf(v.y * s_ss[c4 + 1] + s_ss[16 + c4 + 1], 0.f);
                float x2 = fmaxf(v.z * s_ss[c4 + 2] + s_ss[16 + c4 + 2], 0.f);
                float x3 = fmaxf(v.w * s_ss[c4 + 3] + s_ss[16 + c4 + 3], 0.f);
                const float* w0 = wk + (c4 + 0) * 16;
                const float* w1p = wk + (c4 + 1) * 16;
                const float* w2 = wk + (c4 + 2) * 16;
                const float* w3 = wk + (c4 + 3) * 16;
                #pragma unroll
                for (int o = 0; o < 16; o++)
                    acc[o] += x0 * w0[o] + x1 * w1p[o] + x2 * w2[o] + x3 * w3[o];
            }
        }
        float4* dst = reinterpret_cast<float4*>(&g_xa[j * 16]);
        #pragma unroll
        for (int qq = 0; qq < 4; qq++)
            dst[qq] = make_float4(acc[qq * 4], acc[qq * 4 + 1], acc[qq * 4 + 2], acc[qq * 4 + 3]);
    }
    // BN1 partials: re-read own rows
    {
        float s[16], q[16];
        #pragma unroll
        for (int c = 0; c < 16; c++) { s[c] = 0.f; q[c] = 0.f; }
        for (int j = gid; j < NV; j += STRIDE) {
            const float4* rr = reinterpret_cast<const float4*>(&g_xa[j * 16]);
            #pragma unroll
            for (int qq = 0; qq < 4; qq++) {
                float4 v = rr[qq];
                int c4 = qq * 4;
                s[c4 + 0] += v.x; q[c4 + 0] += v.x * v.x;
                s[c4 + 1] += v.y; q[c4 + 1] += v.y * v.y;
                s[c4 + 2] += v.z; q[c4 + 2] += v.z * v.z;
                s[c4 + 3] += v.w; q[c4 + 3] += v.w * v.w;
            }
        }
        bn_publish(s, q, g_p1, s_red);
    }
    GBAR();  // 3: xa complete

    // ---- Phase E: BN1 finalize, chunk-prefix, rank lookup + affine + dup out, cleanup ----
    // NOTE: rank lookup derives bucket counts from the scan (s1 - s0), NOT from
    // g_bfill — g_bfill is being concurrently cleared by faster blocks below.
    bn_finalize_par(g_p1, g1, b1, s_ss, s_redd);
    if (tid < NCHUNK) s_cpref[tid] = g_bsum[tid];
    __syncthreads();
    if (tid == 0) {
        int run = 0;
        #pragma unroll 1
        for (int k = 0; k < NCHUNK; k++) { int v = s_cpref[k]; s_cpref[k] = run; run += v; }
    }
    __syncthreads();
    for (int j = gid; j < NV; j += STRIDE) {
        int l = g_lin[j];
        int bk = l >> BSHIFT;
        int s0 = s_cpref[bk >> 9] + g_scan[bk];
        int s1 = (bk + 1 == NBK) ? NV : (s_cpref[(bk + 1) >> 9] + g_scan[bk + 1]);
        int cnt = s1 - s0;               // bucket count from scan difference (race-free)
        int bb = bk << 5;
        int c = 0;
        for (int t = 0; t < cnt; t++) c += (g_blin2[bb + t] < l);
        int r = s0 + c;                  // global rank of lin_j
        const float4* xr = reinterpret_cast<const float4*>(&g_xa[r * 16]);
        float4* d0 = reinterpret_cast<float4*>(&out[(size_t)j * 16]);
        float4* d1 = reinterpret_cast<float4*>(&out[(size_t)(j + NV) * 16]);
        #pragma unroll
        for (int qq = 0; qq < 4; qq++) {
            float4 v = xr[qq];
            int c4 = qq * 4;
            v.x = fmaxf(v.x * s_ss[c4 + 0] + s_ss[16 + c4 + 0], 0.f);
            v.y = fmaxf(v.y * s_ss[c4 + 1] + s_ss[16 + c4 + 1], 0.f);
            v.z = fmaxf(v.z * s_ss[c4 + 2] + s_ss[16 + c4 + 2], 0.f);
            v.w = fmaxf(v.w * s_ss[c4 + 3] + s_ss[16 + c4 + 3], 0.f);
            d0[qq] = v;
            d1[qq] = v;
        }
        g_hkey[g_slot[j]] = 0;   // clear hash slot for next replay (not read this phase)
    }
    for (int i = gid; i < NBK; i += STRIDE) g_bfill[i] = 0;   // not read this phase
}

extern "C" void kernel_launch(void* const* d_in, const int* in_sizes, int n_in,
                              void* d_out, int out_size) {
    const float* feats = (const float*)d_in[0];
    const int*   inds  = (const int*)d_in[1];
    const float* w_in  = (const float*)d_in[2];
    const float* g0    = (const float*)d_in[3];
    const float* b0    = (const float*)d_in[4];
    const float* w1    = (const float*)d_in[5];
    const float* g1    = (const float*)d_in[6];
    const float* b1    = (const float*)d_in[7];
    // w2/g2/b2 (d_in[8..10]) are dead in the reference: cat_tensors' inverse
    // indices only ever select rows of xa.
    float* out = (float*)d_out;

    mega<<<GRID, TB>>>(feats, inds, w_in, g0, b0, w1, g1, b1, out);
}

// round 11
// speedup vs baseline: 1.6170x; 1.2985x over previous
#include <cuda_runtime.h>
#include <cstdint>

// Problem constants (fixed by the reference setup)
#define NV 150000          // total active voxels
#define SZc 41
#define SYc 1600
#define SXc 1408
#define HBITS 19
#define HSIZE (1 << HBITS) // 524288 hash slots; empty = 0
#define HMASK (HSIZE - 1)
#define BSHIFT 13
#define NBK 45100          // rank buckets; max lin 369,459,199 -> bucket 45099
#define BCAP 32            // bucket capacity (avg fill 3.3; overflow P ~ 1e-20)
#define NCHUNK 89          // ceil(NBK/512) scan chunks
#define GRID 592           // 4 CTAs/SM x 148 SMs, all co-resident; STRIDE >= NV
#define TB 256
#define STRIDE (GRID * TB)

// ---------------- static device scratch (zero-initialized; kernel leaves it clean) ----------------
__device__ unsigned long long g_h[HSIZE];  // packed ((lin+1)<<18)|row; 0 = empty
__device__ int   g_slot[NV];
__device__ int   g_lin[NV];
__device__ int   g_cnt[NV];          // rulebook count; overwritten with rank in phase D
__device__ int   g_nbr[NV * 27];     // packed (k<<18)|row
__device__ int   g_bfill[NBK];       // bucket fill counts (cleared at end)
__device__ int   g_blin2[NBK * BCAP];// bucket contents (lins, unordered)
__device__ int   g_scan[NBK];        // chunk-local exclusive scan of bucket counts
__device__ int   g_bsum[NCHUNK];     // chunk aggregates
__device__ float g_y0[NV * 16];
__device__ float g_xa[NV * 16];
__device__ float g_p0[GRID * 32];    // conv0 BN partials
__device__ float g_p1[GRID * 32];    // conv1 BN partials
__device__ unsigned g_cbar;          // barrier counter (self-resets to 0)
__device__ unsigned g_sbar;          // barrier sense (persists; read at kernel start)

__device__ __forceinline__ unsigned hash_of(int key) {
    return ((unsigned)key * 2654435761u) >> (32 - HBITS);
}

// Global barrier: sense-reversing, self-resetting. All GRID blocks co-resident.
#define GBAR() do {                                                         \
    __threadfence();                                                        \
    __syncthreads();                                                        \
    if (tid == 0) {                                                         \
        unsigned ns = s_sense ^ 1u;                                         \
        s_sense = ns;                                                       \
        if (atomicAdd(&g_cbar, 1u) == GRID - 1u) {                          \
            g_cbar = 0u;                                                    \
            __threadfence();                                                \
            *(volatile unsigned*)&g_sbar = ns;                              \
        } else {                                                            \
            while (*(volatile unsigned*)&g_sbar != ns) __nanosleep(32);     \
        }                                                                   \
    }                                                                       \
    __syncthreads();                                                        \
    __threadfence();                                                        \
} while (0)

// Deterministic per-block BN partial publish from per-thread acc: tree + cross-warp.
__device__ __forceinline__ void bn_publish_acc(const float acc[16],
                                               float* part, float sred[8][32]) {
    int tid = threadIdx.x;
    float s[16], q[16];
    #pragma unroll
    for (int c = 0; c < 16; c++) { s[c] = acc[c]; q[c] = acc[c] * acc[c]; }
    #pragma unroll
    for (int c = 0; c < 16; c++) {
        #pragma unroll
        for (int off = 16; off > 0; off >>= 1) {
            s[c] += __shfl_down_sync(0xffffffffu, s[c], off);
            q[c] += __shfl_down_sync(0xffffffffu, q[c], off);
        }
    }
    int wp = tid >> 5, lane = tid & 31;
    if (lane == 0) {
        #pragma unroll
        for (int c = 0; c < 16; c++) { sred[wp][c] = s[c]; sred[wp][16 + c] = q[c]; }
    }
    __syncthreads();
    if (wp == 0) {
        float t = 0.f;
        #pragma unroll
        for (int k = 0; k < 8; k++) t += sred[k][lane];
        part[blockIdx.x * 32 + lane] = t;
    }
    __syncthreads();
}

// Redundant PER-BLOCK parallel finalize, bitwise deterministic:
// 8 groups sum fixed strided subsets of the GRID partials, fixed-order combine.
__device__ __forceinline__ void bn_finalize_par(const float* part,
                                                const float* __restrict__ g,
                                                const float* __restrict__ b,
                                                float* s_ss, double sredd[8][32]) {
    int tid = threadIdx.x;
    int col = tid & 31, grp = tid >> 5;
    double a = 0.0;
    for (int k = grp; k < GRID; k += 8) a += (double)part[k * 32 + col];
    sredd[grp][col] = a;
    __syncthreads();
    if (tid < 32) {
        double t = 0.0;
        #pragma unroll
        for (int gg = 0; gg < 8; gg++) t += sredd[gg][tid];
        sredd[0][tid] = t;
    }
    __syncthreads();
    if (tid < 16) {
        double m = sredd[0][tid] / (double)NV;
        double v = sredd[0][16 + tid] / (double)NV - m * m;
        double inv = 1.0 / sqrt(v + 1e-3);
        float sc = g[tid] * (float)inv;
        s_ss[tid] = sc;
        s_ss[16 + tid] = b[tid] - (float)m * sc;
    }
    __syncthreads();
}

__global__ __launch_bounds__(TB, 4) void mega(
    const float* __restrict__ feats, const int* __restrict__ inds,
    const float* __restrict__ w_in,
    const float* __restrict__ g0, const float* __restrict__ b0,
    const float* __restrict__ w1,
    const float* __restrict__ g1, const float* __restrict__ b1,
    float* __restrict__ out)
{
    __shared__ float  s_w[27 * 256];    // conv weights (conv0 uses first 27*64)
    __shared__ float  s_red[8][32];     // BN publish staging
    __shared__ double s_redd[8][32];    // BN finalize staging
    __shared__ int    s_scan[256];
    __shared__ float  s_ss[32];         // scale[16], shift[16]
    __shared__ int    s_cpref[NCHUNK];  // exclusive prefix of chunk aggregates
    __shared__ unsigned s_sense;

    const int tid = threadIdx.x;
    const int j   = blockIdx.x * TB + tid;   // EXACTLY one voxel per thread
    const int b   = blockIdx.x;
    const bool live = (j < NV);

    if (tid == 0) s_sense = *(volatile unsigned*)&g_sbar;
    __syncthreads();

    // ---- Phase A: linearize + fused 64-bit hash insert + bucket scatter ----
    int l = 0;
    if (live) {
        int4 id = reinterpret_cast<const int4*>(inds)[j];
        l = ((id.x * SZc + id.y) * SYc + id.z) * SXc + id.w;
        g_lin[j] = l;
        unsigned long long want = ((unsigned long long)(unsigned)(l + 1) << 18) | (unsigned)j;
        unsigned slot = hash_of(l);
        while (true) {
            unsigned long long old = atomicCAS(&g_h[slot], 0ULL, want);
            if (old == 0ULL) { g_slot[j] = slot; break; }
            slot = (slot + 1) & HMASK;
        }
        int bk = l >> BSHIFT;
        int p = atomicAdd(&g_bfill[bk], 1);
        g_blin2[(bk << 5) + p] = l;
    }
    GBAR();  // 1: hash + buckets complete

    // ---- Phase C: chunk scan (first 89 blocks) overlapped with rulebook + conv0 ----
    for (int i = tid; i < 27 * 64; i += TB) s_w[i] = w_in[i];   // conv0 weights
    if (b < NCHUNK) {
        int base = b * 512;
        int i0 = base + 2 * tid, i1 = i0 + 1;
        int v0 = (i0 < NBK) ? g_bfill[i0] : 0;
        int v1 = (i1 < NBK) ? g_bfill[i1] : 0;
        int ps = v0 + v1;
        s_scan[tid] = ps;
        __syncthreads();
        for (int off = 1; off < 256; off <<= 1) {
            int x = (tid >= off) ? s_scan[tid - off] : 0;
            __syncthreads();
            if (tid >= off) s_scan[tid] += x;
            __syncthreads();
        }
        int incl = s_scan[tid];
        int ex = incl - ps;
        if (i0 < NBK) g_scan[i0] = ex;
        if (i1 < NBK) g_scan[i1] = ex + v0;
        if (tid == 255) g_bsum[b] = incl;
    }
    __syncthreads();

    float acc[16];
    #pragma unroll
    for (int o = 0; o < 16; o++) acc[o] = 0.f;
    if (live) {
        int4 id = reinterpret_cast<const int4*>(inds)[j];
        int c = 0;
        int base = j * 27;
        #pragma unroll
        for (int dz = -1; dz <= 1; dz++) {
            int z = id.y + dz;
            #pragma unroll
            for (int dy = -1; dy <= 1; dy++) {
                int y = id.z + dy;
                #pragma unroll
                for (int dx = -1; dx <= 1; dx++) {
                    int r = -1;
                    int k = ((dz + 1) * 3 + (dy + 1)) * 3 + (dx + 1);
                    if (dz == 0 && dy == 0 && dx == 0) {
                        r = j;
                    } else {
                        int x = id.w + dx;
                        if (z < 0 || z >= SZc || y < 0 || y >= SYc || x < 0 || x >= SXc) continue;
                        int nl = ((id.x * SZc + z) * SYc + y) * SXc + x;
                        unsigned slot = hash_of(nl);
                        unsigned keyw = (unsigned)(nl + 1);
                        while (true) {
                            unsigned long long e = g_h[slot];          // single fused load
                            if (e == 0ULL) break;
                            if ((unsigned)(e >> 18) == keyw) { r = (int)(e & 0x3FFFFULL); break; }
                            slot = (slot + 1) & HMASK;
                        }
                        if (r < 0) continue;
                    }
                    g_nbr[base + c] = (k << 18) | r;
                    c++;
                    float4 f = reinterpret_cast<const float4*>(feats)[r];
                    const float* wk = &s_w[k * 64];
                    #pragma unroll
                    for (int o = 0; o < 16; o++)
                        acc[o] += f.x * wk[o] + f.y * wk[16 + o] + f.z * wk[32 + o] + f.w * wk[48 + o];
                }
            }
        }
        g_cnt[j] = c;
        float4* dst = reinterpret_cast<float4*>(&g_y0[j * 16]);
        #pragma unroll
        for (int qq = 0; qq < 4; qq++)
            dst[qq] = make_float4(acc[qq * 4], acc[qq * 4 + 1], acc[qq * 4 + 2], acc[qq * 4 + 3]);
    }
    bn_publish_acc(acc, g_p0, s_red);   // partial is exactly this thread's row
    GBAR();  // 2: y0, cnt, nbr, scan, bsum complete

    // ---- Phase D: BN0 finalize, conv1 (inline BN0+ReLU on gathers), rank precompute ----
    bn_finalize_par(g_p0, g0, b0, s_ss, s_redd);
    if (tid < NCHUNK) s_cpref[tid] = g_bsum[tid];
    __syncthreads();
    if (tid == 0) {
        int run = 0;
        #pragma unroll 1
        for (int k = 0; k < NCHUNK; k++) { int v = s_cpref[k]; s_cpref[k] = run; run += v; }
    }
    for (int i = tid; i < 27 * 256; i += TB) s_w[i] = w1[i];
    __syncthreads();
    #pragma unroll
    for (int o = 0; o < 16; o++) acc[o] = 0.f;
    if (live) {
        int cn = g_cnt[j];
        int base = j * 27;
        for (int i = 0; i < cn; i++) {
            int p = g_nbr[base + i];
            int k = p >> 18;
            int r = p & 0x3FFFF;
            const float4* xr = reinterpret_cast<const float4*>(&g_y0[r * 16]);
            const float* wk = &s_w[k * 256];
            #pragma unroll
            for (int qq = 0; qq < 4; qq++) {
                float4 v = xr[qq];
                int c4 = qq * 4;
                float x0 = fmaxf(v.x * s_ss[c4 + 0] + s_ss[16 + c4 + 0], 0.f);
                float x1 = fmaxf(v.y * s_ss[c4 + 1] + s_ss[16 + c4 + 1], 0.f);
                float x2 = fmaxf(v.z * s_ss[c4 + 2] + s_ss[16 + c4 + 2], 0.f);
                float x3 = fmaxf(v.w * s_ss[c4 + 3] + s_ss[16 + c4 + 3], 0.f);
                const float* w0 = wk + (c4 + 0) * 16;
                const float* w1p = wk + (c4 + 1) * 16;
                const float* w2 = wk + (c4 + 2) * 16;
                const float* w3 = wk + (c4 + 3) * 16;
                #pragma unroll
                for (int o = 0; o < 16; o++)
                    acc[o] += x0 * w0[o] + x1 * w1p[o] + x2 * w2[o] + x3 * w3[o];
            }
        }
        float4* dst = reinterpret_cast<float4*>(&g_xa[j * 16]);
        #pragma unroll
        for (int qq = 0; qq < 4; qq++)
            dst[qq] = make_float4(acc[qq * 4], acc[qq * 4 + 1], acc[qq * 4 + 2], acc[qq * 4 + 3]);

        // rank precompute (scan + buckets final since GBAR2); overwrite g_cnt after last read
        int ll = g_lin[j];
        int bk = ll >> BSHIFT;
        int s0 = s_cpref[bk >> 9] + g_scan[bk];
        int s1 = (bk + 1 == NBK) ? NV : (s_cpref[(bk + 1) >> 9] + g_scan[bk + 1]);
        int cntb = s1 - s0;
        int bb = bk << 5;
        int cc = 0;
        for (int t = 0; t < cntb; t++) cc += (g_blin2[bb + t] < ll);
        g_cnt[j] = s0 + cc;              // global rank of lin_j
    }
    bn_publish_acc(acc, g_p1, s_red);
    GBAR();  // 3: xa + ranks complete

    // ---- Phase E: BN1 finalize, gather-by-rank + affine + duplicated out, cleanup ----
    bn_finalize_par(g_p1, g1, b1, s_ss, s_redd);
    if (live) {
        int r = g_cnt[j];
        const float4* xr = reinterpret_cast<const float4*>(&g_xa[r * 16]);
        float4* d0 = reinterpret_cast<float4*>(&out[(size_t)j * 16]);
        float4* d1 = reinterpret_cast<float4*>(&out[(size_t)(j + NV) * 16]);
        #pragma unroll
        for (int qq = 0; qq < 4; qq++) {
            float4 v = xr[qq];
            int c4 = qq * 4;
            v.x = fmaxf(v.x * s_ss[c4 + 0] + s_ss[16 + c4 + 0], 0.f);
            v.y = fmaxf(v.y * s_ss[c4 + 1] + s_ss[16 + c4 + 1], 0.f);
            v.z = fmaxf(v.z * s_ss[c4 + 2] + s_ss[16 + c4 + 2], 0.f);
            v.w = fmaxf(v.w * s_ss[c4 + 3] + s_ss[16 + c4 + 3], 0.f);
            d0[qq] = v;
            d1[qq] = v;
        }
        g_h[g_slot[j]] = 0ULL;   // clear hash slot for next replay (not read this phase)
    }
    for (int i = j; i < NBK; i += STRIDE) g_bfill[i] = 0;   // not read this phase
}

extern "C" void kernel_launch(void* const* d_in, const int* in_sizes, int n_in,
                              void* d_out, int out_size) {
    const float* feats = (const float*)d_in[0];
    const int*   inds  = (const int*)d_in[1];
    const float* w_in  = (const float*)d_in[2];
    const float* g0    = (const float*)d_in[3];
    const float* b0    = (const float*)d_in[4];
    const float* w1    = (const float*)d_in[5];
    const float* g1    = (const float*)d_in[6];
    const float* b1    = (const float*)d_in[7];
    // w2/g2/b2 (d_in[8..10]) are dead in the reference: cat_tensors' inverse
    // indices only ever select rows of xa.
    float* out = (float*)d_out;

    mega<<<GRID, TB>>>(feats, inds, w_in, g0, b0, w1, g1, b1, out);
}

// round 13
// speedup vs baseline: 1.6883x; 1.0441x over previous
#include <cuda_runtime.h>
#include <cstdint>

// Problem constants (fixed by the reference setup)
#define NV 150000          // total active voxels
#define SZc 41
#define SYc 1600
#define SXc 1408
#define HBITS 19
#define HSIZE (1 << HBITS) // 524288 hash slots; empty = 0
#define HMASK (HSIZE - 1)
#define BSHIFT 13
#define NBK 45100          // rank buckets; max lin 369,459,199 -> bucket 45099
#define BCAP 32            // bucket capacity (avg fill 3.3; overflow P ~ 1e-20)
#define NCHUNK 89          // ceil(NBK/512) scan chunks
#define GRID 592           // 4 CTAs/SM x 148 SMs, all co-resident; GRID*TB >= NV
#define TB 256
#define STRIDE (GRID * TB)

// ---------------- static device scratch (zero-initialized; kernel leaves it clean) ----------------
__device__ unsigned long long g_h[HSIZE];  // packed ((lin+1)<<18)|row; 0 = empty
__device__ int   g_cnt[NV];          // rulebook count (phase C..D)
__device__ int   g_nbr[NV * 27];     // packed (k<<18)|row
__device__ int   g_inv[NV];          // rank inverse: g_inv[rank(lin_j)] = j  (phase D -> E)
__device__ int   g_bfill[NBK];       // bucket fill counts (cleared at end)
__device__ int   g_blin2[NBK * BCAP];// bucket contents (lins, unordered)
__device__ int   g_scan[NBK];        // chunk-local exclusive scan of bucket counts
__device__ int   g_bsum[NCHUNK];     // chunk aggregates
__device__ float g_y0[NV * 16];
__device__ float g_p0[GRID * 32];    // conv0 BN partials
__device__ float g_p1[GRID * 32];    // conv1 BN partials
__device__ unsigned g_cbar;          // barrier counter (self-resets to 0)
__device__ unsigned g_sbar;          // barrier sense (persists; read at kernel start)

__device__ __forceinline__ unsigned hash_of(int key) {
    return ((unsigned)key * 2654435761u) >> (32 - HBITS);
}

// Global barrier: sense-reversing, self-resetting. All GRID blocks co-resident.
#define GBAR() do {                                                         \
    __threadfence();                                                        \
    __syncthreads();                                                        \
    if (tid == 0) {                                                         \
        unsigned ns = s_sense ^ 1u;                                         \
        s_sense = ns;                                                       \
        if (atomicAdd(&g_cbar, 1u) == GRID - 1u) {                          \
            g_cbar = 0u;                                                    \
            __threadfence();                                                \
            *(volatile unsigned*)&g_sbar = ns;                              \
        } else {                                                            \
            while (*(volatile unsigned*)&g_sbar != ns) __nanosleep(32);     \
        }                                                                   \
    }                                                                       \
    __syncthreads();                                                        \
    __threadfence();                                                        \
} while (0)

// Deterministic per-block BN partial publish from per-thread acc: tree + cross-warp.
__device__ __forceinline__ void bn_publish_acc(const float acc[16],
                                               float* part, float sred[8][32]) {
    int tid = threadIdx.x;
    float s[16], q[16];
    #pragma unroll
    for (int c = 0; c < 16; c++) { s[c] = acc[c]; q[c] = acc[c] * acc[c]; }
    #pragma unroll
    for (int c = 0; c < 16; c++) {
        #pragma unroll
        for (int off = 16; off > 0; off >>= 1) {
            s[c] += __shfl_down_sync(0xffffffffu, s[c], off);
            q[c] += __shfl_down_sync(0xffffffffu, q[c], off);
        }
    }
    int wp = tid >> 5, lane = tid & 31;
    if (lane == 0) {
        #pragma unroll
        for (int c = 0; c < 16; c++) { sred[wp][c] = s[c]; sred[wp][16 + c] = q[c]; }
    }
    __syncthreads();
    if (wp == 0) {
        float t = 0.f;
        #pragma unroll
        for (int k = 0; k < 8; k++) t += sred[k][lane];
        part[blockIdx.x * 32 + lane] = t;
    }
    __syncthreads();
}

// Redundant PER-BLOCK parallel finalize, bitwise deterministic:
// 8 groups sum fixed strided subsets of the GRID partials, fixed-order combine.
__device__ __forceinline__ void bn_finalize_par(const float* part,
                                                const float* __restrict__ g,
                                                const float* __restrict__ b,
                                                float* s_ss, double sredd[8][32]) {
    int tid = threadIdx.x;
    int col = tid & 31, grp = tid >> 5;
    double a = 0.0;
    for (int k = grp; k < GRID; k += 8) a += (double)part[k * 32 + col];
    sredd[grp][col] = a;
    __syncthreads();
    if (tid < 32) {
        double t = 0.0;
        #pragma unroll
        for (int gg = 0; gg < 8; gg++) t += sredd[gg][tid];
        sredd[0][tid] = t;
    }
    __syncthreads();
    if (tid < 16) {
        double m = sredd[0][tid] / (double)NV;
        double v = sredd[0][16 + tid] / (double)NV - m * m;
        double inv = 1.0 / sqrt(v + 1e-3);
        float sc = g[tid] * (float)inv;
        s_ss[tid] = sc;
        s_ss[16 + tid] = b[tid] - (float)m * sc;
    }
    __syncthreads();
}

__global__ __launch_bounds__(TB, 4) void mega(
    const float* __restrict__ feats, const int* __restrict__ inds,
    const float* __restrict__ w_in,
    const float* __restrict__ g0, const float* __restrict__ b0,
    const float* __restrict__ w1,
    const float* __restrict__ g1, const float* __restrict__ b1,
    float* __restrict__ out)
{
    __shared__ float  s_w[27 * 256];    // conv weights (conv0 uses first 27*64)
    __shared__ float  s_red[8][32];     // BN publish staging
    __shared__ double s_redd[8][32];    // BN finalize staging
    __shared__ int    s_scan[256];
    __shared__ float  s_ss[32];         // scale[16], shift[16]
    __shared__ int    s_cpref[NCHUNK];  // exclusive prefix of chunk aggregates
    __shared__ unsigned s_sense;

    const int tid = threadIdx.x;
    const int j   = blockIdx.x * TB + tid;   // EXACTLY one voxel per thread
    const int b   = blockIdx.x;
    const bool live = (j < NV);

    if (tid == 0) s_sense = *(volatile unsigned*)&g_sbar;
    __syncthreads();

    // ---- Phase A: linearize + fused 64-bit hash insert + bucket scatter ----
    int l = 0;                 // lin of voxel j (register-resident for whole kernel)
    unsigned myslot = 0;       // this voxel's hash slot (register-resident)
    if (live) {
        int4 id = reinterpret_cast<const int4*>(inds)[j];
        l = ((id.x * SZc + id.y) * SYc + id.z) * SXc + id.w;
        unsigned long long want = ((unsigned long long)(unsigned)(l + 1) << 18) | (unsigned)j;
        unsigned slot = hash_of(l);
        while (true) {
            unsigned long long old = atomicCAS(&g_h[slot], 0ULL, want);
            if (old == 0ULL) { myslot = slot; break; }
            slot = (slot + 1) & HMASK;
        }
        int bk = l >> BSHIFT;
        int p = atomicAdd(&g_bfill[bk], 1);
        g_blin2[(bk << 5) + p] = l;
    }
    GBAR();  // 1: hash + buckets complete

    // ---- Phase C: chunk scan (first 89 blocks) overlapped with rulebook + conv0 ----
    for (int i = tid; i < 27 * 64; i += TB) s_w[i] = w_in[i];   // conv0 weights
    if (b < NCHUNK) {
        int base = b * 512;
        int i0 = base + 2 * tid, i1 = i0 + 1;
        int v0 = (i0 < NBK) ? g_bfill[i0] : 0;
        int v1 = (i1 < NBK) ? g_bfill[i1] : 0;
        int ps = v0 + v1;
        s_scan[tid] = ps;
        __syncthreads();
        for (int off = 1; off < 256; off <<= 1) {
            int x = (tid >= off) ? s_scan[tid - off] : 0;
            __syncthreads();
            if (tid >= off) s_scan[tid] += x;
            __syncthreads();
        }
        int incl = s_scan[tid];
        int ex = incl - ps;
        if (i0 < NBK) g_scan[i0] = ex;
        if (i1 < NBK) g_scan[i1] = ex + v0;
        if (tid == 255) g_bsum[b] = incl;
    }
    __syncthreads();

    float acc[16];
    #pragma unroll
    for (int o = 0; o < 16; o++) acc[o] = 0.f;
    if (live) {
        int4 id = reinterpret_cast<const int4*>(inds)[j];
        int c = 0;
        int base = j * 27;
        #pragma unroll
        for (int dz = -1; dz <= 1; dz++) {
            int z = id.y + dz;
            #pragma unroll
            for (int dy = -1; dy <= 1; dy++) {
                int y = id.z + dy;
                #pragma unroll
                for (int dx = -1; dx <= 1; dx++) {
                    int r = -1;
                    int k = ((dz + 1) * 3 + (dy + 1)) * 3 + (dx + 1);
                    if (dz == 0 && dy == 0 && dx == 0) {
                        r = j;
                    } else {
                        int x = id.w + dx;
                        if (z < 0 || z >= SZc || y < 0 || y >= SYc || x < 0 || x >= SXc) continue;
                        int nl = ((id.x * SZc + z) * SYc + y) * SXc + x;
                        unsigned slot = hash_of(nl);
                        unsigned keyw = (unsigned)(nl + 1);
                        while (true) {
                            unsigned long long e = g_h[slot];          // single fused load
                            if (e == 0ULL) break;
                            if ((unsigned)(e >> 18) == keyw) { r = (int)(e & 0x3FFFFULL); break; }
                            slot = (slot + 1) & HMASK;
                        }
                        if (r < 0) continue;
                    }
                    g_nbr[base + c] = (k << 18) | r;
                    c++;
                    float4 f = reinterpret_cast<const float4*>(feats)[r];
                    const float* wk = &s_w[k * 64];
                    #pragma unroll
                    for (int o = 0; o < 16; o++)
                        acc[o] += f.x * wk[o] + f.y * wk[16 + o] + f.z * wk[32 + o] + f.w * wk[48 + o];
                }
            }
        }
        g_cnt[j] = c;
        float4* dst = reinterpret_cast<float4*>(&g_y0[j * 16]);
        #pragma unroll
        for (int qq = 0; qq < 4; qq++)
            dst[qq] = make_float4(acc[qq * 4], acc[qq * 4 + 1], acc[qq * 4 + 2], acc[qq * 4 + 3]);
    }
    bn_publish_acc(acc, g_p0, s_red);   // partial is exactly this thread's row
    GBAR();  // 2: y0, cnt, nbr, scan, bsum complete

    // ---- Phase D: BN0 finalize, conv1 (inline BN0+ReLU on gathers), rank-inverse scatter ----
    bn_finalize_par(g_p0, g0, b0, s_ss, s_redd);
    if (tid < NCHUNK) s_cpref[tid] = g_bsum[tid];
    __syncthreads();
    if (tid == 0) {
        int run = 0;
        #pragma unroll 1
        for (int k = 0; k < NCHUNK; k++) { int v = s_cpref[k]; s_cpref[k] = run; run += v; }
    }
    for (int i = tid; i < 27 * 256; i += TB) s_w[i] = w1[i];
    __syncthreads();
    #pragma unroll
    for (int o = 0; o < 16; o++) acc[o] = 0.f;   // conv1 output lives in regs through GBAR3
    if (live) {
        int cn = g_cnt[j];
        int base = j * 27;
        for (int i = 0; i < cn; i++) {
            int p = g_nbr[base + i];
            int k = p >> 18;
            int r = p & 0x3FFFF;
            const float4* xr = reinterpret_cast<const float4*>(&g_y0[r * 16]);
            const float* wk = &s_w[k * 256];
            #pragma unroll
            for (int qq = 0; qq < 4; qq++) {
                float4 v = xr[qq];
                int c4 = qq * 4;
                float x0 = fmaxf(v.x * s_ss[c4 + 0] + s_ss[16 + c4 + 0], 0.f);
                float x1 = fmaxf(v.y * s_ss[c4 + 1] + s_ss[16 + c4 + 1], 0.f);
                float x2 = fmaxf(v.z * s_ss[c4 + 2] + s_ss[16 + c4 + 2], 0.f);
                float x3 = fmaxf(v.w * s_ss[c4 + 3] + s_ss[16 + c4 + 3], 0.f);
                const float* w0 = wk + (c4 + 0) * 16;
                const float* w1p = wk + (c4 + 1) * 16;
                const float* w2 = wk + (c4 + 2) * 16;
                const float* w3 = wk + (c4 + 3) * 16;
                #pragma unroll
                for (int o = 0; o < 16; o++)
                    acc[o] += x0 * w0[o] + x1 * w1p[o] + x2 * w2[o] + x3 * w3[o];
            }
        }
        // rank of lin_j (scan + buckets final since GBAR2); publish rank INVERSE:
        // ranks are a bijection on [0,NV), so g_inv[r_j] = j lets phase E turn the
        // output gather into a register-scatter (no g_xa round-trip at all).
        int bk = l >> BSHIFT;
        int s0 = s_cpref[bk >> 9] + g_scan[bk];
        int s1 = (bk + 1 == NBK) ? NV : (s_cpref[(bk + 1) >> 9] + g_scan[bk + 1]);
        int cntb = s1 - s0;
        int bb = bk << 5;
        int cc = 0;
        for (int t = 0; t < cntb; t++) cc += (g_blin2[bb + t] < l);
        g_inv[s0 + cc] = j;
    }
    bn_publish_acc(acc, g_p1, s_red);
    GBAR();  // 3: conv1 accs published, g_inv complete

    // ---- Phase E: BN1 finalize, register-scatter to out, cleanup ----
    bn_finalize_par(g_p1, g1, b1, s_ss, s_redd);
    if (live) {
        int jj = g_inv[j];   // the output row that needs THIS thread's conv1 value
        float4* d0 = reinterpret_cast<float4*>(&out[(size_t)jj * 16]);
        float4* d1 = reinterpret_cast<float4*>(&out[(size_t)(jj + NV) * 16]);
        #pragma unroll
        for (int qq = 0; qq < 4; qq++) {
            int c4 = qq * 4;
            float4 v;
            v.x = fmaxf(acc[c4 + 0] * s_ss[c4 + 0] + s_ss[16 + c4 + 0], 0.f);
            v.y = fmaxf(acc[c4 + 1] * s_ss[c4 + 1] + s_ss[16 + c4 + 1], 0.f);
            v.z = fmaxf(acc[c4 + 2] * s_ss[c4 + 2] + s_ss[16 + c4 + 2], 0.f);
            v.w = fmaxf(acc[c4 + 3] * s_ss[c4 + 3] + s_ss[16 + c4 + 3], 0.f);
            d0[qq] = v;
            d1[qq] = v;
        }
        g_h[myslot] = 0ULL;  // clear hash slot for next replay (not read this phase)
    }
    for (int i = j; i < NBK; i += STRIDE) g_bfill[i] = 0;   // not read this phase
}

extern "C" void kernel_launch(void* const* d_in, const int* in_sizes, int n_in,
                              void* d_out, int out_size) {
    const float* feats = (const float*)d_in[0];
    const int*   inds  = (const int*)d_in[1];
    const float* w_in  = (const float*)d_in[2];
    const float* g0    = (const float*)d_in[3];
    const float* b0    = (const float*)d_in[4];
    const float* w1    = (const float*)d_in[5];
    const float* g1    = (const float*)d_in[6];
    const float* b1    = (const float*)d_in[7];
    // w2/g2/b2 (d_in[8..10]) are dead in the reference: cat_tensors' inverse
    // indices only ever select rows of xa.
    float* out = (float*)d_out;

    mega<<<GRID, TB>>>(feats, inds, w_in, g0, b0, w1, g1, b1, out);
}